// round 5
// baseline (speedup 1.0000x reference)
#include <cuda_runtime.h>
#include <cuda_bf16.h>

// ============================================================================
// 2-layer LSTM language model, B=32, S=512, E=H=1024, V=32000.
//
//   prep:  weights fp32 -> bf16 transposed+permuted; embedding gather -> bf16;
//          zero h[0]; reset counters (runs every graph replay).
//   main:  persistent kernel, 128 CTAs (64 per layer), pipelined via monotone
//          counters. Per CTA per step: 64x32x2048 bf16 mma.sync GEMM + LSTM
//          cell for 16 hidden units; c-state in registers.
//   tail:  FC -> logits into d_out, then in-place softmax.
// ============================================================================

#define B_     32
#define S_     512
#define H_     1024
#define V_     32000
#define KTOT   2048
#define GPL    64            // CTAs per layer
#define KCHUNK 128
#define NCHUNK (KTOT / KCHUNK)   // 16
#define BSTRIDE 2056         // smem B row stride in halves (4112B: 16B-aligned, conflict-free)
#define ASTRIDE 136          // smem A row stride in halves (272B: 16B-aligned, conflict-free)

// ---------------------------- device scratch -------------------------------
__device__ __nv_bfloat16 g_Wt0[(size_t)4096 * 2048];   // layer0: [r][k] bf16
__device__ __nv_bfloat16 g_Wt1[(size_t)4096 * 2048];   // layer1
__device__ __nv_bfloat16 g_emb[(size_t)S_ * B_ * H_];  // [t][b][k]
__device__ __nv_bfloat16 g_h0[(size_t)(S_ + 1) * B_ * H_]; // [t][b][k]
__device__ __nv_bfloat16 g_h1[(size_t)(S_ + 1) * B_ * H_];
__device__ unsigned g_cnt0;
__device__ unsigned g_cnt1;

// ---------------------------- smem layout ----------------------------------
struct SmemLSTM {
    __nv_bfloat16 B[32][BSTRIDE];      // 131584 B : full B tile [b][k] for one step
    __nv_bfloat16 A[2][64][ASTRIDE];   //  34816 B : double-buffered A chunks [row][k]
    float         z[4][16][33];        //   8448 B : z staging [gate][u][b]
};
// total 174848 B -> 1 CTA / SM

// ---------------------------- helpers ---------------------------------------
__device__ __forceinline__ unsigned smem_u32(const void* p) {
    return (unsigned)__cvta_generic_to_shared(p);
}

__device__ __forceinline__ void cp16(void* dst, const void* src) {
    unsigned d = smem_u32(dst);
    asm volatile("cp.async.cg.shared.global [%0], [%1], 16;\n" :: "r"(d), "l"(src) : "memory");
}

__device__ __forceinline__ unsigned ld_acq(const unsigned* p) {
    unsigned v;
    asm volatile("ld.acquire.gpu.global.u32 %0, [%1];" : "=r"(v) : "l"(p) : "memory");
    return v;
}

__device__ __forceinline__ void load_A_chunk(SmemLSTM* S, const __nv_bfloat16* Wt,
                                             int cg, int chunk, int buf, int tid) {
    // 64 rows x 128 halves = 1024 x 16B units; 8 units per thread
    const __nv_bfloat16* base = Wt + (size_t)cg * 64 * KTOT + chunk * KCHUNK;
    #pragma unroll
    for (int m = 0; m < 8; ++m) {
        int c   = tid + (m << 7);     // 0..1023
        int row = c >> 4;             // 0..63
        int seg = (c & 15) << 3;      // halves: 0..120 step 8
        cp16(&S->A[buf][row][seg], base + (size_t)row * KTOT + seg);
    }
}

// ---------------------------- prep kernels ----------------------------------
__global__ void prep_weights(const float* __restrict__ Wx, const float* __restrict__ Wh,
                             int layer) {
    __nv_bfloat16* __restrict__ Wt = layer ? g_Wt1 : g_Wt0;
    const size_t n = (size_t)4096 * 2048;
    for (size_t idx = (size_t)blockIdx.x * blockDim.x + threadIdx.x; idx < n;
         idx += (size_t)gridDim.x * blockDim.x) {
        int r = (int)(idx >> 11);
        int k = (int)(idx & 2047);
        int cgp = r >> 6, rem = r & 63;
        int gate = rem >> 4, uu = rem & 15;
        int j = gate * H_ + cgp * 16 + uu;   // column in original [K][4096] weight
        float v = (k < H_) ? Wx[(size_t)k * 4096 + j]
                           : Wh[(size_t)(k - H_) * 4096 + j];
        Wt[idx] = __float2bfloat16(v);
    }
}

__global__ void prep_embed(const int* __restrict__ x, const float* __restrict__ emb) {
    const size_t n = (size_t)S_ * B_ * H_;
    for (size_t idx = (size_t)blockIdx.x * blockDim.x + threadIdx.x; idx < n;
         idx += (size_t)gridDim.x * blockDim.x) {
        int t   = (int)(idx >> 15);
        int rem = (int)(idx & 32767);
        int b   = rem >> 10;
        int k   = rem & 1023;
        int tok = x[b * S_ + t];   // x is [B][S]
        g_emb[idx] = __float2bfloat16(emb[(size_t)tok * H_ + k]);
    }
}

__global__ void prep_init() {
    const int n = B_ * H_;
    for (int idx = blockIdx.x * blockDim.x + threadIdx.x; idx < n;
         idx += gridDim.x * blockDim.x) {
        g_h0[idx] = __float2bfloat16(0.f);
        g_h1[idx] = __float2bfloat16(0.f);
    }
    if (blockIdx.x == 0 && threadIdx.x == 0) { g_cnt0 = 0u; g_cnt1 = 0u; }
}

// ---------------------------- persistent LSTM -------------------------------
__global__ void __launch_bounds__(128, 1)
lstm_persistent(const float* __restrict__ bias0, const float* __restrict__ bias1) {
    extern __shared__ __align__(16) char smem_raw[];
    SmemLSTM* S = reinterpret_cast<SmemLSTM*>(smem_raw);

    const int tid  = threadIdx.x;
    const int lane = tid & 31;
    const int g    = tid >> 5;                 // warp index == gate index (i,f,g,o)
    const int cta  = blockIdx.x;
    const bool l1  = (cta >= GPL);
    const int cg   = l1 ? (cta - GPL) : cta;   // 0..63, owns hidden units [cg*16, cg*16+16)

    const __nv_bfloat16* __restrict__ Wt  = l1 ? g_Wt1 : g_Wt0;
    const float* __restrict__ bias        = l1 ? bias1 : bias0;
    unsigned* myCnt                       = l1 ? &g_cnt1 : &g_cnt0;
    __nv_bfloat16* hout                   = l1 ? g_h1 : g_h0;

    // cell-update ownership: thread -> one hidden unit u, four batches
    const int u_loc = tid >> 3;                // 0..15
    const int u_g   = cg * 16 + u_loc;
    const int bb    = (tid & 7) << 2;          // batch base 0..28
    const float bi  = bias[u_g];
    const float bf_ = bias[H_ + u_g];
    const float bg_ = bias[2 * H_ + u_g];
    const float bo_ = bias[3 * H_ + u_g];
    float c_st[4] = {0.f, 0.f, 0.f, 0.f};

    // ldmatrix lane addressing (constant per thread)
    const int a_row  = g * 16 + (lane & 15);
    const int a_kofs = (lane < 16) ? 0 : 8;
    const int l16    = lane & 15;
    const int b_rloc = l16 & 7;
    const int b_kofs = (l16 >> 3) << 3;

    for (int t = 0; t < S_; ++t) {
        // ---- acquire: wait for producers ----
        if (tid == 0) {
            if (!l1) {
                const unsigned tgt = 64u * (unsigned)t;          // peers' step t-1 done
                while (ld_acq(&g_cnt0) < tgt) __nanosleep(64);
            } else {
                const unsigned tgt0 = 64u * (unsigned)(t + 1);   // h0[t+1] available
                while (ld_acq(&g_cnt0) < tgt0) __nanosleep(64);
                const unsigned tgt1 = 64u * (unsigned)t;         // h1[t] available
                while (ld_acq(&g_cnt1) < tgt1) __nanosleep(64);
            }
        }
        __syncthreads();
        __threadfence();

        // ---- B tile: [b][k] = concat(x_input, h_hidden), 128KB via cp.async ----
        const __nv_bfloat16* __restrict__ srcX =
            l1 ? (g_h0 + (size_t)(t + 1) * (B_ * H_)) : (g_emb + (size_t)t * (B_ * H_));
        const __nv_bfloat16* __restrict__ srcH =
            l1 ? (g_h1 + (size_t)t * (B_ * H_)) : (g_h0 + (size_t)t * (B_ * H_));
        #pragma unroll
        for (int m = 0; m < 64; ++m) {
            int c = tid + (m << 7);          // 0..8191 16B units
            int b = c >> 8;                  // 0..31
            int k = (c & 255) << 3;          // 0..2040 halves
            const __nv_bfloat16* src =
                (k < H_) ? (srcX + b * H_ + k) : (srcH + b * H_ + (k - H_));
            cp16(&S->B[b][k], src);
        }
        asm volatile("cp.async.commit_group;\n" ::: "memory");   // group: B
        load_A_chunk(S, Wt, cg, 0, 0, tid);
        asm volatile("cp.async.commit_group;\n" ::: "memory");   // group: A0

        float acc[4][4];
        #pragma unroll
        for (int nt = 0; nt < 4; ++nt)
            #pragma unroll
            for (int q = 0; q < 4; ++q) acc[nt][q] = 0.f;

        // ---- K loop: 16 chunks of 128, double-buffered A ----
        for (int i = 0; i < NCHUNK; ++i) {
            const int buf = i & 1;
            if (i + 1 < NCHUNK) {
                load_A_chunk(S, Wt, cg, i + 1, (i + 1) & 1, tid);
                asm volatile("cp.async.commit_group;\n" ::: "memory");
                asm volatile("cp.async.wait_group 1;\n" ::: "memory");
            } else {
                asm volatile("cp.async.wait_group 0;\n" ::: "memory");
            }
            __syncthreads();

            #pragma unroll
            for (int kt = 0; kt < KCHUNK / 16; ++kt) {
                unsigned a0, a1, a2, a3;
                {
                    unsigned addr = smem_u32(&S->A[buf][a_row][kt * 16 + a_kofs]);
                    asm volatile(
                        "ldmatrix.sync.aligned.m8n8.x4.shared.b16 {%0,%1,%2,%3}, [%4];\n"
                        : "=r"(a0), "=r"(a1), "=r"(a2), "=r"(a3) : "r"(addr));
                }
                const int kglob = i * KCHUNK + kt * 16;
                #pragma unroll
                for (int nt = 0; nt < 4; ++nt) {
                    unsigned bq0, bq1;
                    unsigned baddr = smem_u32(&S->B[nt * 8 + b_rloc][kglob + b_kofs]);
                    asm volatile(
                        "ldmatrix.sync.aligned.m8n8.x2.shared.b16 {%0,%1}, [%2];\n"
                        : "=r"(bq0), "=r"(bq1) : "r"(baddr));
                    asm volatile(
                        "mma.sync.aligned.m16n8k16.row.col.f32.bf16.bf16.f32 "
                        "{%0,%1,%2,%3}, {%4,%5,%6,%7}, {%8,%9}, {%0,%1,%2,%3};\n"
                        : "+f"(acc[nt][0]), "+f"(acc[nt][1]),
                          "+f"(acc[nt][2]), "+f"(acc[nt][3])
                        : "r"(a0), "r"(a1), "r"(a2), "r"(a3), "r"(bq0), "r"(bq1));
                }
            }
            __syncthreads();
        }

        // ---- stage z to smem: warp g -> z[g][u][b] ----
        {
            const int r  = lane >> 2;
            const int cb = (lane & 3) << 1;
            #pragma unroll
            for (int nt = 0; nt < 4; ++nt) {
                S->z[g][r][nt * 8 + cb]         = acc[nt][0];
                S->z[g][r][nt * 8 + cb + 1]     = acc[nt][1];
                S->z[g][r + 8][nt * 8 + cb]     = acc[nt][2];
                S->z[g][r + 8][nt * 8 + cb + 1] = acc[nt][3];
            }
        }
        __syncthreads();

        // ---- LSTM cell update (fp32, c-state in registers) ----
        __nv_bfloat16* hw = hout + (size_t)(t + 1) * (B_ * H_);
        #pragma unroll
        for (int j = 0; j < 4; ++j) {
            const int b = bb + j;
            float zi = S->z[0][u_loc][b] + bi;
            float zf = S->z[1][u_loc][b] + bf_;
            float zg = S->z[2][u_loc][b] + bg_;
            float zo = S->z[3][u_loc][b] + bo_;
            float ig = 1.f / (1.f + __expf(-zi));
            float fg = 1.f / (1.f + __expf(-zf));
            float og = 1.f / (1.f + __expf(-zo));
            float gc = tanhf(zg);
            c_st[j] = fg * c_st[j] + ig * gc;
            hw[b * H_ + u_g] = __float2bfloat16(og * tanhf(c_st[j]));
        }

        // ---- release ----
        __threadfence();
        __syncthreads();
        if (tid == 0) atomicAdd(myCnt, 1u);
    }
}

// ---------------------------- FC + softmax ----------------------------------
__global__ void fc_kernel(const float* __restrict__ Wfc, const float* __restrict__ bfc,
                          float* __restrict__ out) {
    __shared__ float hs[32][129];
    const int tidx = threadIdx.x;
    const int v = blockIdx.x * 256 + tidx;   // grid = 125 -> exactly 32000
    float acc[32];
    #pragma unroll
    for (int b = 0; b < 32; ++b) acc[b] = 0.f;

    const __nv_bfloat16* __restrict__ h1 = g_h1 + (size_t)S_ * B_ * H_;
    for (int kt = 0; kt < 8; ++kt) {
        __syncthreads();
        for (int e = tidx; e < 32 * 128; e += 256) {
            int b = e >> 7, kk = e & 127;
            hs[b][kk] = __bfloat162float(h1[b * H_ + kt * 128 + kk]);
        }
        __syncthreads();
        const float* w = Wfc + (size_t)(kt * 128) * V_ + v;
        #pragma unroll 4
        for (int kk = 0; kk < 128; ++kk) {
            float wv = w[(size_t)kk * V_];
            #pragma unroll
            for (int b = 0; b < 32; ++b) acc[b] += hs[b][kk] * wv;
        }
    }
    const float bias = bfc[v];
    #pragma unroll
    for (int b = 0; b < 32; ++b) out[(size_t)b * V_ + v] = acc[b] + bias;
}

__global__ void softmax_kernel(float* __restrict__ out) {
    const int b = blockIdx.x;                 // 32 rows
    float* row = out + (size_t)b * V_;
    __shared__ float sdata[32];
    const int tid = threadIdx.x;

    float m = -3.4e38f;
    for (int v = tid; v < V_; v += 256) m = fmaxf(m, row[v]);
    #pragma unroll
    for (int o = 16; o; o >>= 1) m = fmaxf(m, __shfl_xor_sync(0xffffffffu, m, o));
    if ((tid & 31) == 0) sdata[tid >> 5] = m;
    __syncthreads();
    if (tid == 0) {
        float mm = sdata[0];
        for (int i = 1; i < 8; ++i) mm = fmaxf(mm, sdata[i]);
        sdata[16] = mm;
    }
    __syncthreads();
    m = sdata[16];

    float s = 0.f;
    for (int v = tid; v < V_; v += 256) s += expf(row[v] - m);
    #pragma unroll
    for (int o = 16; o; o >>= 1) s += __shfl_xor_sync(0xffffffffu, s, o);
    if ((tid & 31) == 0) sdata[tid >> 5] = s;
    __syncthreads();
    if (tid == 0) {
        float ss = 0.f;
        for (int i = 0; i < 8; ++i) ss += sdata[i];
        sdata[17] = ss;
    }
    __syncthreads();
    const float inv = 1.f / sdata[17];

    for (int v = tid; v < V_; v += 256) row[v] = expf(row[v] - m) * inv;
}

// ---------------------------- launch -----------------------------------------
extern "C" void kernel_launch(void* const* d_in, const int* in_sizes, int n_in,
                              void* d_out, int out_size) {
    const int*   x   = (const int*)d_in[0];
    const float* emb = (const float*)d_in[1];
    const float* Wx0 = (const float*)d_in[2];
    const float* Wh0 = (const float*)d_in[3];
    const float* b0  = (const float*)d_in[4];
    const float* Wx1 = (const float*)d_in[5];
    const float* Wh1 = (const float*)d_in[6];
    const float* b1  = (const float*)d_in[7];
    const float* Wfc = (const float*)d_in[8];
    const float* bfc = (const float*)d_in[9];
    float* out = (float*)d_out;

    cudaFuncSetAttribute(lstm_persistent,
                         cudaFuncAttributeMaxDynamicSharedMemorySize,
                         (int)sizeof(SmemLSTM));

    prep_weights<<<2048, 256>>>(Wx0, Wh0, 0);
    prep_weights<<<2048, 256>>>(Wx1, Wh1, 1);
    prep_embed<<<2048, 256>>>(x, emb);
    prep_init<<<64, 256>>>();
    lstm_persistent<<<128, 128, sizeof(SmemLSTM)>>>(b0, b1);
    fc_kernel<<<125, 256>>>(Wfc, bfc, out);
    softmax_kernel<<<32, 256>>>(out);
}